// round 1
// baseline (speedup 1.0000x reference)
#include <cuda_runtime.h>
#include <cstdint>

#define N_NODES 50000
#define N_EDGES 625000
#define F 128          // F_IN == F_OUT == 128

// Scratch: support = x @ W  (25.6 MB). __device__ global => allocation-free.
__device__ float g_support[(size_t)N_NODES * F];

// ---------------------------------------------------------------------------
// Kernel 1: out[n][f] = bias[f]   (re-init every call; d_out is poisoned)
// ---------------------------------------------------------------------------
__global__ void init_out_kernel(float* __restrict__ out, const float* __restrict__ bias) {
    int i = blockIdx.x * blockDim.x + threadIdx.x;       // float4 index
    const int n4 = N_NODES * F / 4;                      // 1.6M
    if (i < n4) {
        const float4* b4 = (const float4*)bias;          // 32 float4 per row
        ((float4*)out)[i] = b4[i & 31];
    }
}

// ---------------------------------------------------------------------------
// Kernel 2: support = x @ W
// Block: 256 threads, tile 32 rows x 128 cols.
//   warp g (=tid/32) owns rows [4g, 4g+4); lane q (=tid%32) owns cols [4q, 4q+4)
//   -> 16 fp32 accumulators per thread, FFMA-bound.
// x tile cached in smem; reads are warp-uniform (broadcast, conflict-free).
// W column loads are coalesced float4; W = 64KB -> L1-resident.
// ---------------------------------------------------------------------------
__global__ __launch_bounds__(256) void gemm_kernel(const float* __restrict__ x,
                                                   const float* __restrict__ w) {
    __shared__ float xs[32][F];                          // 16 KB
    const int m0 = blockIdx.x * 32;
    const int t  = threadIdx.x;

    // Cooperative load of x tile (32*128 floats = 1024 float4, 256 threads)
    {
        float4* xdst = (float4*)&xs[0][0];
        const int nvec = 32 * F / 4;                     // 1024
        #pragma unroll
        for (int i = t; i < nvec; i += 256) {
            int row = i >> 5;                            // 32 float4 per row
            if (m0 + row < N_NODES)
                xdst[i] = ((const float4*)(x + (size_t)m0 * F))[i];
            else
                xdst[i] = make_float4(0.f, 0.f, 0.f, 0.f);
        }
    }
    __syncthreads();

    const int q = t & 31;                                // col quad
    const int g = t >> 5;                                // row group (== warp id)

    float acc[4][4];
    #pragma unroll
    for (int i = 0; i < 4; i++)
        #pragma unroll
        for (int j = 0; j < 4; j++) acc[i][j] = 0.f;

    const float4* __restrict__ w4 = (const float4*)w;    // w[k*F + c] -> w4[k*32 + q]

    #pragma unroll 2
    for (int k = 0; k < F; k += 4) {
        // 4 rows x 4 k-values of x, via float4 smem reads (warp-uniform broadcast)
        float xr[4][4];
        #pragma unroll
        for (int i = 0; i < 4; i++) {
            float4 xv = *(const float4*)&xs[g * 4 + i][k];
            xr[i][0] = xv.x; xr[i][1] = xv.y; xr[i][2] = xv.z; xr[i][3] = xv.w;
        }
        #pragma unroll
        for (int kk = 0; kk < 4; kk++) {
            float4 wv = w4[(size_t)(k + kk) * 32 + q];
            #pragma unroll
            for (int i = 0; i < 4; i++) {
                acc[i][0] += xr[i][kk] * wv.x;
                acc[i][1] += xr[i][kk] * wv.y;
                acc[i][2] += xr[i][kk] * wv.z;
                acc[i][3] += xr[i][kk] * wv.w;
            }
        }
    }

    #pragma unroll
    for (int i = 0; i < 4; i++) {
        int m = m0 + g * 4 + i;
        if (m < N_NODES) {
            float4 v = make_float4(acc[i][0], acc[i][1], acc[i][2], acc[i][3]);
            *(float4*)&g_support[(size_t)m * F + q * 4] = v;
        }
    }
}

// ---------------------------------------------------------------------------
// Kernel 3: scatter-add. One warp per edge:
//   lane f: out[r][4f..4f+3] += v * support[c][4f..4f+3]  via red.global.add.v4.f32
// support is L2-resident (25.6 MB), so the random gather is an L2 hit.
// ---------------------------------------------------------------------------
__global__ __launch_bounds__(256) void spmm_kernel(const float* __restrict__ vals,
                                                   const int*   __restrict__ rows,
                                                   const int*   __restrict__ cols,
                                                   float*       __restrict__ out) {
    const int warp = (blockIdx.x * blockDim.x + threadIdx.x) >> 5;
    const int lane = threadIdx.x & 31;
    if (warp >= N_EDGES) return;

    const int   c = cols[warp];
    const int   r = rows[warp];
    const float v = vals[warp];

    const float4 s = *(const float4*)&g_support[(size_t)c * F + lane * 4];
    float4 m;
    m.x = s.x * v; m.y = s.y * v; m.z = s.z * v; m.w = s.w * v;

    float* dst = out + (size_t)r * F + lane * 4;
    asm volatile("red.global.add.v4.f32 [%0], {%1, %2, %3, %4};"
                 :: "l"(dst), "f"(m.x), "f"(m.y), "f"(m.z), "f"(m.w)
                 : "memory");
}

// ---------------------------------------------------------------------------
// Launch. Inputs (metadata order): 0=x, 1=weight, 2=bias, 3=edge_vals,
//                                  4=edge_rows, 5=edge_cols
// ---------------------------------------------------------------------------
extern "C" void kernel_launch(void* const* d_in, const int* in_sizes, int n_in,
                              void* d_out, int out_size) {
    const float* x    = (const float*)d_in[0];
    const float* w    = (const float*)d_in[1];
    const float* bias = (const float*)d_in[2];
    const float* vals = (const float*)d_in[3];
    const int*   rows = (const int*)d_in[4];
    const int*   cols = (const int*)d_in[5];
    float*       out  = (float*)d_out;

    // out = bias (broadcast)
    {
        const int n4 = N_NODES * F / 4;
        init_out_kernel<<<(n4 + 255) / 256, 256>>>(out, bias);
    }

    // support = x @ W
    {
        const int nblocks = (N_NODES + 31) / 32;         // 1563
        gemm_kernel<<<nblocks, 256>>>(x, w);
    }

    // out += A_sparse @ support
    {
        const long long threads = (long long)N_EDGES * 32;
        const int nblocks = (int)((threads + 255) / 256); // 78125
        spmm_kernel<<<nblocks, 256>>>(vals, rows, cols, out);
    }
}